// round 17
// baseline (speedup 1.0000x reference)
#include <cuda_runtime.h>
#include <cuda_bf16.h>
#include <cstdint>

#define BATCH 2
#define T 2048
#define D 1024
#define H 16
#define HD 64

// ---------------- scratch (allocation-free) ----------------
// int8 2-word quantized operands + per-row scales (GEMMs)
__device__ int8_t g_iq1[BATCH*T*D], g_iq2[BATCH*T*D];
__device__ int8_t g_ik1[BATCH*T*D], g_ik2[BATCH*T*D];
__device__ int8_t g_iv1[BATCH*T*D], g_iv2[BATCH*T*D];
__device__ int8_t g_Wq1[D*D], g_Wq2[D*D];
__device__ int8_t g_Wk1[D*D], g_Wk2[D*D];
__device__ int8_t g_Wv1[D*D], g_Wv2[D*D];
__device__ int8_t g_Wo1[D*D], g_Wo2[D*D];
__device__ float g_s_iq[BATCH*T], g_s_ik[BATCH*T], g_s_iv[BATCH*T];
__device__ float g_s_Wq[D], g_s_Wk[D], g_s_Wv[D], g_s_Wo[D];
// attention operands: split-bf16 Q/K ([bh][t][n]) and V transposed ([bh][n][t])
__device__ __nv_bfloat16 g_aQh[BATCH*H*T*HD], g_aQl[BATCH*H*T*HD];
__device__ __nv_bfloat16 g_aKh[BATCH*H*T*HD], g_aKl[BATCH*H*T*HD];
__device__ __nv_bfloat16 g_aVh[BATCH*H*T*HD], g_aVl[BATCH*H*T*HD];
// attention output (fp32) + its quantized form
__device__ float  g_Ofp[BATCH*T*D];
__device__ int8_t g_O1[BATCH*T*D], g_O2[BATCH*T*D];
__device__ float  g_s_O[BATCH*T];

// ---------------- PTX helpers (family-portable: sm_72/80+ only) ------------
__device__ __forceinline__ uint32_t smem_u32(const void* p) {
    uint32_t a;
    asm("{ .reg .u64 t; cvta.to.shared.u64 t, %1; cvt.u32.u64 %0, t; }" : "=r"(a) : "l"(p));
    return a;
}
__device__ __forceinline__ void cp16(uint32_t s, const void* g) {
    asm volatile("cp.async.cg.shared.global [%0], [%1], 16;" :: "r"(s), "l"(g));
}
__device__ __forceinline__ void cp_commit() {
    asm volatile("cp.async.commit_group;" ::: "memory");
}
template<int N> __device__ __forceinline__ void cp_wait() {
    asm volatile("cp.async.wait_group %0;" :: "n"(N) : "memory");
}
__device__ __forceinline__ void ldsm4(uint32_t* r, uint32_t addr) {
    asm volatile("ldmatrix.sync.aligned.m8n8.x4.shared.b16 {%0,%1,%2,%3}, [%4];"
                 : "=r"(r[0]), "=r"(r[1]), "=r"(r[2]), "=r"(r[3]) : "r"(addr));
}
__device__ __forceinline__ void mma16816(float* c, const uint32_t* a, const uint32_t* b) {
    asm volatile(
        "mma.sync.aligned.m16n8k16.row.col.f32.bf16.bf16.f32 "
        "{%0,%1,%2,%3}, {%4,%5,%6,%7}, {%8,%9}, {%0,%1,%2,%3};"
        : "+f"(c[0]), "+f"(c[1]), "+f"(c[2]), "+f"(c[3])
        : "r"(a[0]), "r"(a[1]), "r"(a[2]), "r"(a[3]), "r"(b[0]), "r"(b[1]));
}
__device__ __forceinline__ void imma16832(int* c, const uint32_t* a, const uint32_t* b) {
    asm volatile(
        "mma.sync.aligned.m16n8k32.row.col.s32.s8.s8.s32 "
        "{%0,%1,%2,%3}, {%4,%5,%6,%7}, {%8,%9}, {%0,%1,%2,%3};"
        : "+r"(c[0]), "+r"(c[1]), "+r"(c[2]), "+r"(c[3])
        : "r"(a[0]), "r"(a[1]), "r"(a[2]), "r"(a[3]), "r"(b[0]), "r"(b[1]));
}
__device__ __forceinline__ uint32_t pack_hilo(__nv_bfloat16 lo, __nv_bfloat16 hi) {
    __nv_bfloat162 t(lo, hi);
    return *(uint32_t*)&t;
}

// ---------------- int8 GEMM geometry (BM=128, BN=64, BK=128) ---------------
#define BM 128
#define BN 64
#define BK 128                      // int8: 128 B per row chunk
#define ROWB 144                    // 128 B + 16 pad; 9*16B -> conflict-free ldmatrix
#define A_TILE (128 * ROWB)         // 18432
#define B_TILE (64 * ROWB)          // 9216
#define GA_1 0
#define GA_2 A_TILE
#define GB_1 (2 * A_TILE)
#define GB_2 (2 * A_TILE + B_TILE)
#define BUF_BYTES (2 * A_TILE + 2 * B_TILE)   // 55296
#define GEMM_SMEM (2 * BUF_BYTES)             // 110592
#define GTHREADS 256
#define NCHUNK (D / BK)             // 8
#define INV254 (1.0f / 254.0f)

// ---------------- per-row 2-word int8 quantization --------------------------
__device__ __forceinline__ void quant_row_body(
    const float* __restrict__ src, int8_t* __restrict__ o1, int8_t* __restrict__ o2,
    float* __restrict__ sc, int row)
{
    __shared__ float red[8];
    int tid = threadIdx.x;
    const float* r = src + (size_t)row * D;
    float4 v = *(const float4*)(r + tid * 4);
    float m = fmaxf(fmaxf(fabsf(v.x), fabsf(v.y)), fmaxf(fabsf(v.z), fabsf(v.w)));
    #pragma unroll
    for (int off = 16; off; off >>= 1) m = fmaxf(m, __shfl_xor_sync(0xffffffffu, m, off));
    if ((tid & 31) == 0) red[tid >> 5] = m;
    __syncthreads();
    float mx = red[0];
    #pragma unroll
    for (int w = 1; w < 8; w++) mx = fmaxf(mx, red[w]);
    mx = fmaxf(mx, 1e-20f);
    if (tid == 0) sc[row] = mx / 127.0f;
    float inv = 127.0f / mx;
    float xs[4] = {v.x * inv, v.y * inv, v.z * inv, v.w * inv};
    char q1[4], q2[4];
    #pragma unroll
    for (int j = 0; j < 4; j++) {
        int a = __float2int_rn(xs[j]);
        float rem = xs[j] - (float)a;
        int b2 = __float2int_rn(rem * 254.0f);
        q1[j] = (char)a; q2[j] = (char)b2;
    }
    size_t o = (size_t)row * D + tid * 4;
    *(char4*)(o1 + o) = make_char4(q1[0], q1[1], q1[2], q1[3]);
    *(char4*)(o2 + o) = make_char4(q2[0], q2[1], q2[2], q2[3]);
}

// block = one row of 1024 floats; 16384 blocks cover q,k,v,Wq,Wk,Wv,Wo
__global__ __launch_bounds__(256) void quant_all(
    const float* __restrict__ q, const float* __restrict__ k, const float* __restrict__ v,
    const float* __restrict__ Wq, const float* __restrict__ Wk,
    const float* __restrict__ Wv, const float* __restrict__ Wo)
{
    int b = blockIdx.x;
    if (b < 4096)       quant_row_body(q,  g_iq1, g_iq2, g_s_iq, b);
    else if (b < 8192)  quant_row_body(k,  g_ik1, g_ik2, g_s_ik, b - 4096);
    else if (b < 12288) quant_row_body(v,  g_iv1, g_iv2, g_s_iv, b - 8192);
    else if (b < 13312) quant_row_body(Wq, g_Wq1, g_Wq2, g_s_Wq, b - 12288);
    else if (b < 14336) quant_row_body(Wk, g_Wk1, g_Wk2, g_s_Wk, b - 13312);
    else if (b < 15360) quant_row_body(Wv, g_Wv1, g_Wv2, g_s_Wv, b - 14336);
    else                quant_row_body(Wo, g_Wo1, g_Wo2, g_s_Wo, b - 15360);
}

__global__ __launch_bounds__(256) void quant_O() {
    quant_row_body(g_Ofp, g_O1, g_O2, g_s_O, blockIdx.x);
}

// ---------------- shared IMMA mainloop (128x64, BK=128, 2-word int8) -------
__device__ __forceinline__ void imma_issue(
    uint32_t sb, int buf,
    const int8_t* __restrict__ A1, const int8_t* __restrict__ A2,
    const int8_t* __restrict__ B1, const int8_t* __restrict__ B2,
    int row0, int col0, int kc)
{
    int tid = threadIdx.x;
    uint32_t bb = sb + buf * BUF_BYTES;
    #pragma unroll
    for (int j = 0; j < 4; j++) {
        int idx = tid + j * 256;
        int row = idx >> 3, seg = idx & 7;
        uint32_t so = row * ROWB + seg * 16;
        const size_t go = (size_t)(row0 + row) * D + kc + seg * 16;
        cp16(bb + GA_1 + so, A1 + go);
        cp16(bb + GA_2 + so, A2 + go);
    }
    #pragma unroll
    for (int j = 0; j < 2; j++) {
        int idx = tid + j * 256;
        int row = idx >> 3, seg = idx & 7;
        uint32_t so = row * ROWB + seg * 16;
        const size_t go = (size_t)(col0 + row) * D + kc + seg * 16;
        cp16(bb + GB_1 + so, B1 + go);
        cp16(bb + GB_2 + so, B2 + go);
    }
}

// C/(sA sB) = c1 + c2/254  computed in two s32 accumulator sets
__device__ __forceinline__ void imma_gemm(
    uint32_t sb,
    const int8_t* __restrict__ A1, const int8_t* __restrict__ A2,
    const int8_t* __restrict__ B1, const int8_t* __restrict__ B2,
    int row0, int col0, int c1[2][4][4], int c2[2][4][4])
{
    int tid = threadIdx.x;
    int lane = tid & 31, wid = tid >> 5;
    int m0 = (wid >> 1) * 32, n0 = (wid & 1) * 32;
    int mt = lane >> 3, lr = lane & 7;
    uint32_t aoff = (uint32_t)((m0 + (mt & 1) * 8 + lr) * ROWB + (mt >> 1) * 16);
    uint32_t boff = (uint32_t)((n0 + (mt >> 1) * 8 + lr) * ROWB + (mt & 1) * 16);

    #pragma unroll
    for (int i = 0; i < 2; i++)
        #pragma unroll
        for (int j = 0; j < 4; j++)
            #pragma unroll
            for (int f = 0; f < 4; f++) { c1[i][j][f] = 0; c2[i][j][f] = 0; }

    imma_issue(sb, 0, A1, A2, B1, B2, row0, col0, 0);  cp_commit();
    imma_issue(sb, 1, A1, A2, B1, B2, row0, col0, BK); cp_commit();

    #pragma unroll 1
    for (int cch = 0; cch < NCHUNK; cch++) {
        if (cch < NCHUNK - 1) cp_wait<1>(); else cp_wait<0>();
        __syncthreads();
        uint32_t bufb = sb + (cch & 1) * BUF_BYTES;

        #pragma unroll
        for (int kk = 0; kk < BK; kk += 32) {
            uint32_t b1f[4][2], b2f[4][2];
            #pragma unroll
            for (int jp = 0; jp < 2; jp++) {
                uint32_t r[4];
                ldsm4(r, bufb + GB_1 + boff + jp * 16 * ROWB + kk);
                b1f[2*jp][0] = r[0]; b1f[2*jp][1] = r[1];
                b1f[2*jp+1][0] = r[2]; b1f[2*jp+1][1] = r[3];
                ldsm4(r, bufb + GB_2 + boff + jp * 16 * ROWB + kk);
                b2f[2*jp][0] = r[0]; b2f[2*jp][1] = r[1];
                b2f[2*jp+1][0] = r[2]; b2f[2*jp+1][1] = r[3];
            }
            #pragma unroll
            for (int i = 0; i < 2; i++) {
                uint32_t a1[4], a2[4];
                ldsm4(a1, bufb + GA_1 + aoff + i * 16 * ROWB + kk);
                ldsm4(a2, bufb + GA_2 + aoff + i * 16 * ROWB + kk);
                #pragma unroll
                for (int j = 0; j < 4; j++) imma16832(c1[i][j], a1, b1f[j]);  // hh
                #pragma unroll
                for (int j = 0; j < 4; j++) imma16832(c2[i][j], a1, b2f[j]);  // h*lo
                #pragma unroll
                for (int j = 0; j < 4; j++) imma16832(c2[i][j], a2, b1f[j]);  // lo*h
            }
        }
        __syncthreads();
        if (cch + 2 < NCHUNK) { imma_issue(sb, cch & 1, A1, A2, B1, B2, row0, col0, (cch + 2) * BK); cp_commit(); }
    }
}

// ---------------- projection GEMM: dequant epilogue emits split-bf16 Q/K + V^T
__global__ __launch_bounds__(GTHREADS, 2)
void proj_hmma() {
    extern __shared__ char sm[];
    uint32_t sb = smem_u32(sm);
    const int8_t *A1, *A2, *B1, *B2; const float *sA, *sB;
    int z = blockIdx.z;
    if (z == 0)      { A1 = g_iq1; A2 = g_iq2; B1 = g_Wq1; B2 = g_Wq2; sA = g_s_iq; sB = g_s_Wq; }
    else if (z == 1) { A1 = g_ik1; A2 = g_ik2; B1 = g_Wk1; B2 = g_Wk2; sA = g_s_ik; sB = g_s_Wk; }
    else             { A1 = g_iv1; A2 = g_iv2; B1 = g_Wv1; B2 = g_Wv2; sA = g_s_iv; sB = g_s_Wv; }
    int row0 = blockIdx.y * BM, col0 = blockIdx.x * BN;

    int c1[2][4][4], c2[2][4][4];
    imma_gemm(sb, A1, A2, B1, B2, row0, col0, c1, c2);

    int lane = threadIdx.x & 31, wid = threadIdx.x >> 5;
    int m0 = (wid >> 1) * 32, n0 = (wid & 1) * 32;
    int trow = lane >> 2, tcol = (lane & 3) * 2;
    #pragma unroll
    for (int i = 0; i < 2; i++) {
        #pragma unroll
        for (int half = 0; half < 2; half++) {
            int row = row0 + m0 + 16 * i + trow + half * 8;
            int bb = row >> 11, tt = row & 2047;
            float sa = sA[row];
            #pragma unroll
            for (int j = 0; j < 4; j++) {
                int col = col0 + n0 + 8 * j + tcol;
                int h = col >> 6, d = col & 63;
                size_t bh_ = (size_t)bb * H + h;
                float sb0 = sa * sB[col], sb1 = sa * sB[col + 1];
                float v0 = sb0 * ((float)c1[i][j][half*2+0] + (float)c2[i][j][half*2+0] * INV254);
                float v1 = sb1 * ((float)c1[i][j][half*2+1] + (float)c2[i][j][half*2+1] * INV254);
                __nv_bfloat16 h0 = __float2bfloat16(v0);
                __nv_bfloat16 h1 = __float2bfloat16(v1);
                __nv_bfloat16 l0 = __float2bfloat16(v0 - __bfloat162float(h0));
                __nv_bfloat16 l1 = __float2bfloat16(v1 - __bfloat162float(h1));
                if (z == 0) {
                    size_t o = (bh_ * T + tt) * HD + d;
                    *(uint32_t*)(g_aQh + o) = pack_hilo(h0, h1);
                    *(uint32_t*)(g_aQl + o) = pack_hilo(l0, l1);
                } else if (z == 1) {
                    size_t o = (bh_ * T + tt) * HD + d;
                    *(uint32_t*)(g_aKh + o) = pack_hilo(h0, h1);
                    *(uint32_t*)(g_aKl + o) = pack_hilo(l0, l1);
                } else {
                    size_t o0 = (bh_ * HD + d) * T + tt;
                    size_t o1 = (bh_ * HD + d + 1) * T + tt;
                    g_aVh[o0] = h0; g_aVh[o1] = h1;
                    g_aVl[o0] = l0; g_aVl[o1] = l1;
                }
            }
        }
    }
}

// ---------------- output projection GEMM + bias ----------------
__global__ __launch_bounds__(GTHREADS, 2)
void out_hmma(const float* __restrict__ bo, float* __restrict__ dout) {
    extern __shared__ char sm[];
    uint32_t sb = smem_u32(sm);
    int row0 = blockIdx.y * BM, col0 = blockIdx.x * BN;

    int c1[2][4][4], c2[2][4][4];
    imma_gemm(sb, g_O1, g_O2, g_Wo1, g_Wo2, row0, col0, c1, c2);

    int lane = threadIdx.x & 31, wid = threadIdx.x >> 5;
    int m0 = (wid >> 1) * 32, n0 = (wid & 1) * 32;
    int trow = lane >> 2, tcol = (lane & 3) * 2;
    #pragma unroll
    for (int i = 0; i < 2; i++) {
        #pragma unroll
        for (int half = 0; half < 2; half++) {
            int row = row0 + m0 + 16 * i + trow + half * 8;
            float sa = g_s_O[row];
            #pragma unroll
            for (int j = 0; j < 4; j++) {
                int col = col0 + n0 + 8 * j + tcol;
                float2 b2 = *(const float2*)(bo + col);
                float sb0 = sa * g_s_Wo[col], sb1 = sa * g_s_Wo[col + 1];
                float v0 = sb0 * ((float)c1[i][j][half*2+0] + (float)c2[i][j][half*2+0] * INV254) + b2.x;
                float v1 = sb1 * ((float)c1[i][j][half*2+1] + (float)c2[i][j][half*2+1] * INV254) + b2.y;
                *(float2*)(dout + (size_t)row * D + col) = make_float2(v0, v1);
            }
        }
    }
}

// ---------------------------------------------------------------------------
// HMMA flash attention (unchanged from R16 except epilogue -> fp32 O)
// ---------------------------------------------------------------------------
#define ROWK 144
#define AQ_H 0
#define AQ_L 18432
#define KV0  36864
#define KVSTAGE 36864
#define AK_H 0
#define AK_L 9216
#define AV_H 18432
#define AV_L 27648
#define ATT_SMEM (KV0 + 2 * KVSTAGE)   // 110592

__device__ __forceinline__ void attn_fill_kv(uint32_t st, int bh, int kc) {
    int tid = threadIdx.x;
    #pragma unroll
    for (int r = 0; r < 2; r++) {
        int idx = tid + r * 256;
        int row = idx >> 3, seg = idx & 7;
        size_t kb = ((size_t)bh * T + kc + row) * HD + seg * 8;
        size_t vb = ((size_t)bh * HD + row) * T + kc + seg * 8;
        uint32_t so = row * ROWK + seg * 16;
        cp16(st + AK_H + so, g_aKh + kb);
        cp16(st + AK_L + so, g_aKl + kb);
        cp16(st + AV_H + so, g_aVh + vb);
        cp16(st + AV_L + so, g_aVl + vb);
    }
}

__global__ __launch_bounds__(256, 2) void attn_hmma()
{
    extern __shared__ char sm[];
    uint32_t sb = smem_u32(sm);
    int bh = blockIdx.y;
    int qt0 = blockIdx.x * 128;
    int tid = threadIdx.x, lane = tid & 31, warp = tid >> 5;
    int mt = lane >> 3, lr = lane & 7, g = lane >> 2, tig = lane & 3;

    {
        const __nv_bfloat16* qh = g_aQh + ((size_t)bh * T + qt0) * HD;
        const __nv_bfloat16* ql = g_aQl + ((size_t)bh * T + qt0) * HD;
        #pragma unroll
        for (int r = 0; r < 4; r++) {
            int idx = tid + r * 256;
            int row = idx >> 3, seg = idx & 7;
            cp16(sb + AQ_H + row * ROWK + seg * 16, qh + (size_t)row * HD + seg * 8);
            cp16(sb + AQ_L + row * ROWK + seg * 16, ql + (size_t)row * HD + seg * 8);
        }
    }
    attn_fill_kv(sb + KV0, bh, 0);
    cp_commit();

    float o[8][4];
    #pragma unroll
    for (int j = 0; j < 8; j++)
        #pragma unroll
        for (int f = 0; f < 4; f++) o[j][f] = 0.f;
    float m0 = -1e30f, m1 = -1e30f, l0 = 0.f, l1 = 0.f;

    uint32_t aoffQ = (uint32_t)((warp * 16 + (mt & 1) * 8 + lr) * ROWK + ((mt >> 1) * 8) * 2);
    uint32_t boff  = (uint32_t)(((mt >> 1) * 8 + lr) * ROWK + ((mt & 1) * 8) * 2);

    #pragma unroll 1
    for (int ci = 0; ci < 32; ci++) {
        if (ci + 1 < 32) {
            attn_fill_kv(sb + KV0 + ((ci + 1) & 1) * KVSTAGE, bh, (ci + 1) * 64);
            cp_commit();
            cp_wait<1>();
        } else {
            cp_wait<0>();
        }
        __syncthreads();
        uint32_t st = sb + KV0 + (ci & 1) * KVSTAGE;

        float s[8][4];
        #pragma unroll
        for (int j = 0; j < 8; j++)
            #pragma unroll
            for (int f = 0; f < 4; f++) s[j][f] = 0.f;

        #pragma unroll
        for (int kk = 0; kk < 64; kk += 16) {
            uint32_t ah[4], al[4];
            ldsm4(ah, sb + AQ_H + aoffQ + kk * 2);
            ldsm4(al, sb + AQ_L + aoffQ + kk * 2);
            #pragma unroll
            for (int jp2 = 0; jp2 < 2; jp2++) {
                uint32_t kh0[4], kl0[4], kh1[4], kl1[4];
                ldsm4(kh0, st + AK_H + boff + (2*jp2+0) * 16 * ROWK + kk * 2);
                ldsm4(kl0, st + AK_L + boff + (2*jp2+0) * 16 * ROWK + kk * 2);
                ldsm4(kh1, st + AK_H + boff + (2*jp2+1) * 16 * ROWK + kk * 2);
                ldsm4(kl1, st + AK_L + boff + (2*jp2+1) * 16 * ROWK + kk * 2);
                float* s0 = s[4*jp2+0]; float* s1 = s[4*jp2+1];
                float* s2 = s[4*jp2+2]; float* s3 = s[4*jp2+3];
                mma16816(s0, ah, kh0); mma16816(s1, ah, kh0 + 2);
                mma16816(s2, ah, kh1); mma16816(s3, ah, kh1 + 2);
                mma16816(s0, ah, kl0); mma16816(s1, ah, kl0 + 2);
                mma16816(s2, ah, kl1); mma16816(s3, ah, kl1 + 2);
                mma16816(s0, al, kh0); mma16816(s1, al, kh0 + 2);
                mma16816(s2, al, kh1); mma16816(s3, al, kh1 + 2);
            }
        }

        float mx0 = -1e30f, mx1 = -1e30f;
        #pragma unroll
        for (int j = 0; j < 8; j++) {
            s[j][0] *= 0.125f; s[j][1] *= 0.125f; s[j][2] *= 0.125f; s[j][3] *= 0.125f;
            mx0 = fmaxf(mx0, fmaxf(s[j][0], s[j][1]));
            mx1 = fmaxf(mx1, fmaxf(s[j][2], s[j][3]));
        }
        mx0 = fmaxf(mx0, __shfl_xor_sync(0xffffffffu, mx0, 1));
        mx0 = fmaxf(mx0, __shfl_xor_sync(0xffffffffu, mx0, 2));
        mx1 = fmaxf(mx1, __shfl_xor_sync(0xffffffffu, mx1, 1));
        mx1 = fmaxf(mx1, __shfl_xor_sync(0xffffffffu, mx1, 2));
        float nm0 = fmaxf(m0, mx0), nm1 = fmaxf(m1, mx1);
        float al0 = __expf(m0 - nm0), al1 = __expf(m1 - nm1);
        m0 = nm0; m1 = nm1;
        float rs0 = 0.f, rs1 = 0.f;
        #pragma unroll
        for (int j = 0; j < 8; j++) {
            s[j][0] = __expf(s[j][0] - m0); rs0 += s[j][0];
            s[j][1] = __expf(s[j][1] - m0); rs0 += s[j][1];
            s[j][2] = __expf(s[j][2] - m1); rs1 += s[j][2];
            s[j][3] = __expf(s[j][3] - m1); rs1 += s[j][3];
        }
        rs0 += __shfl_xor_sync(0xffffffffu, rs0, 1);
        rs0 += __shfl_xor_sync(0xffffffffu, rs0, 2);
        rs1 += __shfl_xor_sync(0xffffffffu, rs1, 1);
        rs1 += __shfl_xor_sync(0xffffffffu, rs1, 2);
        l0 = l0 * al0 + rs0;
        l1 = l1 * al1 + rs1;
        #pragma unroll
        for (int j = 0; j < 8; j++) {
            o[j][0] *= al0; o[j][1] *= al0; o[j][2] *= al1; o[j][3] *= al1;
        }

        #pragma unroll
        for (int j2 = 0; j2 < 4; j2++) {
            uint32_t aPh[4], aPl[4];
            #pragma unroll
            for (int q2 = 0; q2 < 2; q2++) {
                float p0 = s[2*j2+q2][0], p1 = s[2*j2+q2][1];
                float p2 = s[2*j2+q2][2], p3 = s[2*j2+q2][3];
                __nv_bfloat16 h0 = __float2bfloat16(p0), h1 = __float2bfloat16(p1);
                __nv_bfloat16 h2 = __float2bfloat16(p2), h3 = __float2bfloat16(p3);
                aPh[q2*2+0] = pack_hilo(h0, h1);
                aPh[q2*2+1] = pack_hilo(h2, h3);
                aPl[q2*2+0] = pack_hilo(__float2bfloat16(p0 - __bfloat162float(h0)),
                                        __float2bfloat16(p1 - __bfloat162float(h1)));
                aPl[q2*2+1] = pack_hilo(__float2bfloat16(p2 - __bfloat162float(h2)),
                                        __float2bfloat16(p3 - __bfloat162float(h3)));
            }
            #pragma unroll
            for (int dp2 = 0; dp2 < 2; dp2++) {
                uint32_t vh0[4], vl0[4], vh1[4], vl1[4];
                ldsm4(vh0, st + AV_H + boff + (2*dp2+0) * 16 * ROWK + j2 * 32);
                ldsm4(vl0, st + AV_L + boff + (2*dp2+0) * 16 * ROWK + j2 * 32);
                ldsm4(vh1, st + AV_H + boff + (2*dp2+1) * 16 * ROWK + j2 * 32);
                ldsm4(vl1, st + AV_L + boff + (2*dp2+1) * 16 * ROWK + j2 * 32);
                float* o0 = o[4*dp2+0]; float* o1 = o[4*dp2+1];
                float* o2 = o[4*dp2+2]; float* o3 = o[4*dp2+3];
                mma16816(o0, aPh, vh0); mma16816(o1, aPh, vh0 + 2);
                mma16816(o2, aPh, vh1); mma16816(o3, aPh, vh1 + 2);
                mma16816(o0, aPh, vl0); mma16816(o1, aPh, vl0 + 2);
                mma16816(o2, aPh, vl1); mma16816(o3, aPh, vl1 + 2);
                mma16816(o0, aPl, vh0); mma16816(o1, aPl, vh0 + 2);
                mma16816(o2, aPl, vh1); mma16816(o3, aPl, vh1 + 2);
            }
        }
        __syncthreads();
    }

    // ---- epilogue: O/l -> fp32 at [b][t][h*64+d] ----
    float inv0 = 1.f / l0, inv1 = 1.f / l1;
    int b = bh >> 4, h = bh & 15;
    int tA = qt0 + warp * 16 + g;
    int tB = tA + 8;
    #pragma unroll
    for (int j = 0; j < 8; j++) {
        int d = h * 64 + 8 * j + 2 * tig;
        *(float2*)(g_Ofp + ((size_t)b * T + tA) * D + d) = make_float2(o[j][0] * inv0, o[j][1] * inv0);
        *(float2*)(g_Ofp + ((size_t)b * T + tB) * D + d) = make_float2(o[j][2] * inv1, o[j][3] * inv1);
    }
}

// ---------------------------------------------------------------------------
extern "C" void kernel_launch(void* const* d_in, const int* in_sizes, int n_in,
                              void* d_out, int out_size)
{
    const float* k  = (const float*)d_in[0];
    const float* q  = (const float*)d_in[1];
    const float* v  = (const float*)d_in[2];
    const float* Wk = (const float*)d_in[3];
    const float* Wq = (const float*)d_in[4];
    const float* Wv = (const float*)d_in[5];
    const float* Wo = (const float*)d_in[6];
    const float* bo = (const float*)d_in[7];
    float* out = (float*)d_out;

    cudaFuncSetAttribute(proj_hmma, cudaFuncAttributeMaxDynamicSharedMemorySize, GEMM_SMEM);
    cudaFuncSetAttribute(out_hmma,  cudaFuncAttributeMaxDynamicSharedMemorySize, GEMM_SMEM);
    cudaFuncSetAttribute(attn_hmma, cudaFuncAttributeMaxDynamicSharedMemorySize, ATT_SMEM);

    // 1) quantize inputs + weights to 2-word int8 with per-row scales
    quant_all<<<16384, 256>>>(q, k, v, Wq, Wk, Wv, Wo);

    // 2) Q/K/V projections on int8 tensor cores; epilogue emits split-bf16 Q/K + V^T
    proj_hmma<<<dim3(D/BN, (BATCH*T)/BM, 3), GTHREADS, GEMM_SMEM>>>();

    // 3) flash attention (split-bf16), writes fp32 O
    attn_hmma<<<dim3(T/128, BATCH*H), 256, ATT_SMEM>>>();

    // 4) quantize O, then output projection on int8 tensor cores + bias
    quant_O<<<BATCH*T, 256>>>();
    out_hmma<<<dim3(D/BN, (BATCH*T)/BM), GTHREADS, GEMM_SMEM>>>(bo, out);
}